// round 7
// baseline (speedup 1.0000x reference)
#include <cuda_runtime.h>

#define P 576
#define P2 (P / 2)          // 288 float2 columns
#define NC 3
#define KDIM 4
#define THREADS 288
#define GRID (148 * 7)      // 7 CTAs/SM * 148 SMs = one full wave

__device__ float g_sum[P];      // zero at load; reset by last block each run
__device__ float g_sumsq[P];
__device__ unsigned int g_ticket;  // zero at load; reset by last block

__global__ __launch_bounds__(THREADS, 7) void csoap_fused_kernel(
    const float2* __restrict__ X2,
    const float* __restrict__ mu,
    const float* __restrict__ W,
    float* __restrict__ out,
    int n_rows, int rows_per_block, float inv_n)
{
    const int c = threadIdx.x;          // float2 column 0..287

    int r0 = blockIdx.x * rows_per_block;
    int r1 = r0 + rows_per_block;
    if (r1 > n_rows) r1 = n_rows;

    // ---- per-column accumulation: thread owns 2 adjacent columns (float2),
    //      coalesced LDG.64, 4-way row unroll ----
    float sx = 0.f, sy = 0.f, s2x = 0.f, s2y = 0.f;
    if (r0 < r1) {
        const float2* p = X2 + (size_t)r0 * P2 + c;
        int r = r0;
        for (; r + 4 <= r1; r += 4) {
            float2 a0 = p[0 * P2];
            float2 a1 = p[1 * P2];
            float2 a2 = p[2 * P2];
            float2 a3 = p[3 * P2];
            p += 4 * P2;
            sx  += (a0.x + a1.x) + (a2.x + a3.x);
            sy  += (a0.y + a1.y) + (a2.y + a3.y);
            s2x += (a0.x * a0.x + a1.x * a1.x) + (a2.x * a2.x + a3.x * a3.x);
            s2y += (a0.y * a0.y + a1.y * a1.y) + (a2.y * a2.y + a3.y * a3.y);
        }
        for (; r < r1; r++) {
            float2 a = p[0];
            p += P2;
            sx += a.x;  sy += a.y;
            s2x += a.x * a.x;  s2y += a.y * a.y;
        }
        atomicAdd(&g_sum[2 * c + 0], sx);
        atomicAdd(&g_sum[2 * c + 1], sy);
        atomicAdd(&g_sumsq[2 * c + 0], s2x);
        atomicAdd(&g_sumsq[2 * c + 1], s2y);
    }

    // ---- last-block election ----
    __threadfence();
    __syncthreads();
    __shared__ int is_last;
    if (threadIdx.x == 0)
        is_last = (atomicAdd(&g_ticket, 1u) == (unsigned)(gridDim.x - 1));
    __syncthreads();

    if (!is_last) return;

    // ---- finalize + project: 288 threads cover 576 columns in 2 passes ----
    __shared__ float s_acc[KDIM];
    if (threadIdx.x < KDIM) s_acc[threadIdx.x] = 0.0f;
    __syncthreads();

    float acc[KDIM] = {0.f, 0.f, 0.f, 0.f};

    #pragma unroll
    for (int pass = 0; pass < 2; pass++) {
        int j = threadIdx.x + pass * THREADS;

        float total   = __ldcg(&g_sum[j]);
        float totalsq = __ldcg(&g_sumsq[j]);
        float m    = total * inv_n;
        float mom2 = fmaf(-m, m, totalsq * inv_n);   // E[x^2] - m^2

        // reset scratch for the next graph replay
        g_sum[j]   = 0.0f;
        g_sumsq[j] = 0.0f;

        int jb = j * NC;
        float d0 = m    - mu[jb + 0];
        float d1 = 0.0f - mu[jb + 1];
        float d2 = mom2 - mu[jb + 2];

        #pragma unroll
        for (int k = 0; k < KDIM; k++) {
            acc[k] += d0 * W[(jb + 0) * KDIM + k]
                    + d1 * W[(jb + 1) * KDIM + k]
                    + d2 * W[(jb + 2) * KDIM + k];
        }
    }
    if (threadIdx.x == 0) g_ticket = 0u;

    #pragma unroll
    for (int k = 0; k < KDIM; k++) {
        float v = acc[k];
        #pragma unroll
        for (int off = 16; off > 0; off >>= 1)
            v += __shfl_down_sync(0xFFFFFFFFu, v, off);
        if ((threadIdx.x & 31) == 0)
            atomicAdd(&s_acc[k], v);
    }
    __syncthreads();

    if (threadIdx.x < KDIM) out[threadIdx.x] = s_acc[threadIdx.x];
}

extern "C" void kernel_launch(void* const* d_in, const int* in_sizes, int n_in,
                              void* d_out, int out_size)
{
    const float2* X2 = (const float2*)d_in[0];
    const float* mu  = (const float*)d_in[1];
    const float* W   = (const float*)d_in[2];
    float* out = (float*)d_out;

    int n_rows = in_sizes[0] / P;
    int rows_per_block = (n_rows + GRID - 1) / GRID;

    csoap_fused_kernel<<<GRID, THREADS>>>(X2, mu, W, out, n_rows,
                                          rows_per_block, 1.0f / (float)n_rows);
}

// round 9
// speedup vs baseline: 1.1553x; 1.1553x over previous
#include <cuda_runtime.h>

#define P 576
#define NC 3
#define KDIM 4
#define THREADS 576
#define GRID 444            // 3 CTAs/SM * 148 SMs = exactly one full wave

__device__ float g_sum[P];      // zero at load; reset by last block each run
__device__ float g_sumsq[P];
__device__ unsigned int g_ticket;  // zero at load; reset by last block

__global__ __launch_bounds__(THREADS, 3) void csoap_fused_kernel(
    const float* __restrict__ X,
    const float* __restrict__ mu,
    const float* __restrict__ W,
    float* __restrict__ out,
    int n_rows, int rows_per_block, float inv_n)
{
    const int col = threadIdx.x;

    int r0 = blockIdx.x * rows_per_block;
    int r1 = r0 + rows_per_block;
    if (r1 > n_rows) r1 = n_rows;

    // ---- per-column accumulation: thread owns one column, warp reads exactly
    //      one 128-B line per LDG (1 wavefront, no replays), 4-way unroll ----
    float s = 0.0f, s2 = 0.0f;
    if (r0 < r1) {
        const float* p = X + (size_t)r0 * P + col;
        int r = r0;
        for (; r + 4 <= r1; r += 4) {
            float a0 = p[0 * P];
            float a1 = p[1 * P];
            float a2 = p[2 * P];
            float a3 = p[3 * P];
            p += 4 * P;
            s  += (a0 + a1) + (a2 + a3);
            s2 += (a0 * a0 + a1 * a1) + (a2 * a2 + a3 * a3);
        }
        for (; r < r1; r++) {
            float a = p[0];
            p += P;
            s  += a;
            s2 += a * a;
        }
        atomicAdd(&g_sum[col],   s);
        atomicAdd(&g_sumsq[col], s2);
    }

    // ---- last-block election ----
    __threadfence();
    __syncthreads();
    __shared__ int is_last;
    if (threadIdx.x == 0)
        is_last = (atomicAdd(&g_ticket, 1u) == (unsigned)(gridDim.x - 1));
    __syncthreads();

    if (!is_last) return;

    // ---- finalize + project (576 threads, one per feature column) ----
    __shared__ float s_acc[KDIM];
    const int j = threadIdx.x;
    if (j < KDIM) s_acc[j] = 0.0f;
    __syncthreads();

    float total   = __ldcg(&g_sum[j]);     // L2 read, bypass L1
    float totalsq = __ldcg(&g_sumsq[j]);
    float m    = total * inv_n;
    float mom2 = fmaf(-m, m, totalsq * inv_n);   // E[x^2] - m^2

    // reset scratch for the next graph replay
    g_sum[j]   = 0.0f;
    g_sumsq[j] = 0.0f;
    if (j == 0) g_ticket = 0u;

    int jb = j * NC;
    float d0 = m    - mu[jb + 0];
    float d1 = 0.0f - mu[jb + 1];
    float d2 = mom2 - mu[jb + 2];

    float acc[KDIM];
    #pragma unroll
    for (int k = 0; k < KDIM; k++) {
        acc[k] = d0 * W[(jb + 0) * KDIM + k]
               + d1 * W[(jb + 1) * KDIM + k]
               + d2 * W[(jb + 2) * KDIM + k];
    }

    #pragma unroll
    for (int k = 0; k < KDIM; k++) {
        float v = acc[k];
        #pragma unroll
        for (int off = 16; off > 0; off >>= 1)
            v += __shfl_down_sync(0xFFFFFFFFu, v, off);
        if ((threadIdx.x & 31) == 0)
            atomicAdd(&s_acc[k], v);
    }
    __syncthreads();

    if (j < KDIM) out[j] = s_acc[j];
}

extern "C" void kernel_launch(void* const* d_in, const int* in_sizes, int n_in,
                              void* d_out, int out_size)
{
    const float* X  = (const float*)d_in[0];
    const float* mu = (const float*)d_in[1];
    const float* W  = (const float*)d_in[2];
    float* out = (float*)d_out;

    int n_rows = in_sizes[0] / P;
    int rows_per_block = (n_rows + GRID - 1) / GRID;

    csoap_fused_kernel<<<GRID, THREADS>>>(X, mu, W, out, n_rows,
                                          rows_per_block, 1.0f / (float)n_rows);
}